// round 14
// baseline (speedup 1.0000x reference)
#include <cuda_runtime.h>
#include <cuda_fp16.h>
#include <cstdint>

// MASLoRALinear, fp16 HMMA. R11 prep/lora verbatim. k_main: 128x128 tile,
// 4 warps x (64x64) warp tiles, 128 threads, occ 2 -> smem traffic 96 B/cyc
// (below 128 B/cyc crossbar cap), tensor-bound.

namespace {
constexpr int Tt = 1500, Cc = 1024, Oo = 1024, Ee = 8, Rr = 16;
constexpr int Mm = 16 * Tt;          // 24000
constexpr int ER = Ee * Rr;          // 128
constexpr float SCALE = 32.0f / 16.0f;
constexpr int STAGE = 16384;         // A 8KB + B 8KB (fp16, BK=32)
constexpr int NSTAGE = 3;
constexpr int DYN_SMEM = NSTAGE * STAGE;
}

__device__ __half g_xh[(size_t)Mm * Cc];     // 24000x1024
__device__ __half g_wbh[(size_t)Oo * Cc];    // 1024x1024
__device__ __half g_ah[(size_t)ER * Cc];     // 128x1024 (Acat)
__device__ __half g_bch[(size_t)Oo * ER];    // 1024x128 (Bcat)
__device__ __half g_Hh[(size_t)Mm * ER];     // 24000x128

// ---------------------------------------------------------------------------
__device__ __forceinline__ uint32_t smem_u32(const void* p) {
    uint32_t a;
    asm("{ .reg .u64 t; cvta.to.shared.u64 t, %1; cvt.u32.u64 %0, t; }" : "=r"(a) : "l"(p));
    return a;
}

#define CP16(s, g) \
    asm volatile("cp.async.cg.shared.global [%0], [%1], 16;" :: "r"(s), "l"(g))
#define CP_COMMIT() asm volatile("cp.async.commit_group;" ::: "memory")
#define CP_WAIT1() asm volatile("cp.async.wait_group 1;" ::: "memory")
#define CP_WAIT0() asm volatile("cp.async.wait_group 0;" ::: "memory")

#define LDSM_X4(r0, r1, r2, r3, a) \
    asm volatile("ldmatrix.sync.aligned.m8n8.x4.shared.b16 {%0,%1,%2,%3}, [%4];" \
                 : "=r"(r0), "=r"(r1), "=r"(r2), "=r"(r3) : "r"(a))

#define MMA_F16(d, a, b) \
    asm volatile("mma.sync.aligned.m16n8k16.row.col.f32.f16.f16.f32 " \
                 "{%0,%1,%2,%3},{%4,%5,%6,%7},{%8,%9},{%0,%1,%2,%3};" \
                 : "+f"((d)[0]), "+f"((d)[1]), "+f"((d)[2]), "+f"((d)[3]) \
                 : "r"((a)[0]), "r"((a)[1]), "r"((a)[2]), "r"((a)[3]), \
                   "r"((b)[0]), "r"((b)[1]))

// swizzled byte offset: 64B rows, 4x16B cols, xor swizzle
__device__ __forceinline__ uint32_t swz(int r, int c) {
    return (uint32_t)(r * 64 + ((c ^ ((r >> 1) & 3)) << 4));
}

// ---------------------------------------------------------------------------
// single prep launch: x->xh, Wb->wbh, Acat->ah, Bcat->bch  (R11 verbatim)
// ---------------------------------------------------------------------------
__global__ void k_prep_all(const float* __restrict__ x, const float* __restrict__ Wb,
                           const float* __restrict__ As, const float* __restrict__ Bs) {
    const int stride = gridDim.x * blockDim.x;
    const int gtid = blockIdx.x * blockDim.x + threadIdx.x;

    for (int i = gtid; i < Mm * Cc / 4; i += stride) {
        float4 v = *(const float4*)(x + (size_t)i * 4);
        __half2 h0 = __float22half2_rn(make_float2(v.x, v.y));
        __half2 h1 = __float22half2_rn(make_float2(v.z, v.w));
        *(uint2*)(g_xh + (size_t)i * 4) = make_uint2(*(uint32_t*)&h0, *(uint32_t*)&h1);
    }
    for (int i = gtid; i < Oo * Cc / 4; i += stride) {
        float4 v = *(const float4*)(Wb + (size_t)i * 4);
        __half2 h0 = __float22half2_rn(make_float2(v.x, v.y));
        __half2 h1 = __float22half2_rn(make_float2(v.z, v.w));
        *(uint2*)(g_wbh + (size_t)i * 4) = make_uint2(*(uint32_t*)&h0, *(uint32_t*)&h1);
    }
    for (int i = gtid; i < ER * Cc / 4; i += stride) {
        float4 v = *(const float4*)(As + (size_t)i * 4);
        __half2 h0 = __float22half2_rn(make_float2(v.x, v.y));
        __half2 h1 = __float22half2_rn(make_float2(v.z, v.w));
        *(uint2*)(g_ah + (size_t)i * 4) = make_uint2(*(uint32_t*)&h0, *(uint32_t*)&h1);
    }
    for (int idx = gtid; idx < Oo * ER; idx += stride) {
        int o = idx >> 7, n = idx & 127;
        g_bch[idx] = __float2half(Bs[(((size_t)(n >> 4)) * Oo + o) * Rr + (n & 15)]);
    }
}

// ---------------------------------------------------------------------------
// Kernel 1: Hh = gate-scaled (xh @ ah^T)  (R11 verbatim; 128x128, occ 2)
// ---------------------------------------------------------------------------
__global__ __launch_bounds__(256, 2)
void k_lora_h(const float* __restrict__ w) {
    extern __shared__ char dsm[];
    const uint32_t sb = smem_u32(dsm);
    const int tid = threadIdx.x;
    const int lane = tid & 31, wid = tid >> 5;
    const int wm = wid >> 2, wn = wid & 3;
    const int bm = blockIdx.x * 128;

    const int r0 = tid >> 2, cc4 = tid & 3;
    const __half* xa0 = g_xh + (size_t)min(bm + r0, Mm - 1) * Cc + cc4 * 8;
    const __half* xa1 = g_xh + (size_t)min(bm + r0 + 64, Mm - 1) * Cc + cc4 * 8;
    const __half* ab0 = g_ah + (size_t)r0 * Cc + cc4 * 8;
    const __half* ab1 = g_ah + (size_t)(r0 + 64) * Cc + cc4 * 8;
    const uint32_t o0 = swz(r0, cc4), o1 = swz(r0 + 64, cc4);

    uint32_t offA[8], offB[4];
    {
        int g = lane >> 3, wr = lane & 7;
#pragma unroll
        for (int mi = 0; mi < 4; mi++)
#pragma unroll
            for (int ks = 0; ks < 2; ks++) {
                int r = wm * 64 + mi * 16 + (g & 1) * 8 + wr;
                offA[mi * 2 + ks] = swz(r, ks * 2 + (g >> 1));
            }
#pragma unroll
        for (int j = 0; j < 2; j++)
#pragma unroll
            for (int ks = 0; ks < 2; ks++) {
                int n = wn * 32 + j * 16 + (g >> 1) * 8 + wr;
                offB[j * 2 + ks] = swz(n, ks * 2 + (g & 1));
            }
    }

    float acc[4][4][4];
#pragma unroll
    for (int a = 0; a < 4; a++)
#pragma unroll
        for (int b = 0; b < 4; b++)
#pragma unroll
            for (int c = 0; c < 4; c++) acc[a][b][c] = 0.0f;

    const int NCH = 32;
#pragma unroll
    for (int p = 0; p < 2; p++) {
        uint32_t st = sb + (uint32_t)p * STAGE;
        CP16(st + o0, xa0 + p * 32); CP16(st + o1, xa1 + p * 32);
        CP16(st + 8192u + o0, ab0 + p * 32); CP16(st + 8192u + o1, ab1 + p * 32);
        CP_COMMIT();
    }

#pragma unroll 1
    for (int ch = 0; ch < NCH; ch++) {
        if (ch + 1 < NCH) CP_WAIT1(); else CP_WAIT0();
        __syncthreads();
        if (ch + 2 < NCH) {
            uint32_t st = sb + (uint32_t)((ch + 2) % NSTAGE) * STAGE;
            CP16(st + o0, xa0 + (ch + 2) * 32); CP16(st + o1, xa1 + (ch + 2) * 32);
            CP16(st + 8192u + o0, ab0 + (ch + 2) * 32); CP16(st + 8192u + o1, ab1 + (ch + 2) * 32);
            CP_COMMIT();
        }
        const uint32_t base = sb + (uint32_t)(ch % NSTAGE) * STAGE;
        const uint32_t aB = base, bB = base + 8192u;
#pragma unroll
        for (int ks = 0; ks < 2; ks++) {
            uint32_t aF[4][4], bF[4][2];
#pragma unroll
            for (int mi = 0; mi < 4; mi++)
                LDSM_X4(aF[mi][0], aF[mi][1], aF[mi][2], aF[mi][3], aB + offA[mi * 2 + ks]);
#pragma unroll
            for (int j = 0; j < 2; j++) {
                uint32_t t0, t1, t2, t3;
                LDSM_X4(t0, t1, t2, t3, bB + offB[j * 2 + ks]);
                bF[2 * j][0] = t0; bF[2 * j][1] = t1;
                bF[2 * j + 1][0] = t2; bF[2 * j + 1][1] = t3;
            }
#pragma unroll
            for (int mi = 0; mi < 4; mi++)
#pragma unroll
                for (int ni = 0; ni < 4; ni++)
                    MMA_F16(acc[mi][ni], aF[mi], bF[ni]);
        }
    }

#pragma unroll
    for (int mi = 0; mi < 4; mi++) {
#pragma unroll
        for (int ni = 0; ni < 4; ni++) {
            int n = wn * 32 + ni * 8 + 2 * (lane & 3);
            int e = n >> 4;
            int m0 = bm + wm * 64 + mi * 16 + (lane >> 2);
            if (m0 < Mm) {
                float sw = SCALE * __ldg(&w[(m0 / Tt) * Ee + e]);
                __half2 h = __float22half2_rn(make_float2(acc[mi][ni][0] * sw, acc[mi][ni][1] * sw));
                *(__half2*)(&g_Hh[(size_t)m0 * ER + n]) = h;
            }
            int m1 = m0 + 8;
            if (m1 < Mm) {
                float sw = SCALE * __ldg(&w[(m1 / Tt) * Ee + e]);
                __half2 h = __float22half2_rn(make_float2(acc[mi][ni][2] * sw, acc[mi][ni][3] * sw));
                *(__half2*)(&g_Hh[(size_t)m1 * ER + n]) = h;
            }
        }
    }
}

// ---------------------------------------------------------------------------
// Kernel 2: out = xh @ wbh^T + Hh @ bch^T + bb
// 128x128 tile, 128 threads: 4 warps as 2(M)x2(N), warp tile 64x64.
// 36 chunks of BK=32, 3-stage cp.async, occ 2.
// ---------------------------------------------------------------------------
__global__ __launch_bounds__(128, 2)
void k_main(const float* __restrict__ bb, float* __restrict__ out) {
    extern __shared__ char dsm[];
    const uint32_t sb = smem_u32(dsm);
    const int tid = threadIdx.x;
    const int lane = tid & 31, wid = tid >> 5;
    const int wm = wid >> 1, wn = wid & 1;      // 2x2 warps of 64x64
    const int bn = blockIdx.x * 128;
    const int bm = blockIdx.y * 128;

    // loaders: thread tid owns full 64B row tid of A and of B (4 slots each)
    const size_t mA = (size_t)min(bm + tid, Mm - 1);
    const __half* xa = g_xh + mA * Cc;
    const __half* ha = g_Hh + mA * ER;
    const __half* wb = g_wbh + (size_t)(bn + tid) * Cc;
    const __half* bc = g_bch + (size_t)(bn + tid) * ER;
    uint32_t oS[4];
#pragma unroll
    for (int q = 0; q < 4; q++) oS[q] = swz(tid, q);

    // ldmatrix offsets: A 4 m-tiles, B 4 j-pairs (64 cols)
    uint32_t offA[8], offB[8];
    {
        int g = lane >> 3, wr = lane & 7;
#pragma unroll
        for (int mi = 0; mi < 4; mi++)
#pragma unroll
            for (int ks = 0; ks < 2; ks++) {
                int r = wm * 64 + mi * 16 + (g & 1) * 8 + wr;
                offA[mi * 2 + ks] = swz(r, ks * 2 + (g >> 1));
            }
#pragma unroll
        for (int j = 0; j < 4; j++)
#pragma unroll
            for (int ks = 0; ks < 2; ks++) {
                int n = wn * 64 + j * 16 + (g >> 1) * 8 + wr;
                offB[j * 2 + ks] = swz(n, ks * 2 + (g & 1));
            }
    }

    float acc[4][8][4];
#pragma unroll
    for (int a = 0; a < 4; a++)
#pragma unroll
        for (int b = 0; b < 8; b++)
#pragma unroll
            for (int c = 0; c < 4; c++) acc[a][b][c] = 0.0f;

    const int NCH = 36;

    auto issue = [&](int ch) {
        uint32_t st = sb + (uint32_t)(ch % NSTAGE) * STAGE;
        const __half *pa, *pb;
        if (ch < 32) { pa = xa + ch * 32; pb = wb + ch * 32; }
        else         { pa = ha + (ch - 32) * 32; pb = bc + (ch - 32) * 32; }
#pragma unroll
        for (int q = 0; q < 4; q++) {
            CP16(st + oS[q], pa + q * 8);
            CP16(st + 8192u + oS[q], pb + q * 8);
        }
        CP_COMMIT();
    };

    issue(0);
    issue(1);

#pragma unroll 1
    for (int ch = 0; ch < NCH; ch++) {
        if (ch + 1 < NCH) CP_WAIT1(); else CP_WAIT0();
        __syncthreads();
        if (ch + 2 < NCH) issue(ch + 2);
        const uint32_t base = sb + (uint32_t)(ch % NSTAGE) * STAGE;
        const uint32_t aB = base, bB = base + 8192u;
#pragma unroll
        for (int ks = 0; ks < 2; ks++) {
            uint32_t aF[4][4], bF[8][2];
#pragma unroll
            for (int mi = 0; mi < 4; mi++)
                LDSM_X4(aF[mi][0], aF[mi][1], aF[mi][2], aF[mi][3], aB + offA[mi * 2 + ks]);
#pragma unroll
            for (int j = 0; j < 4; j++) {
                uint32_t t0, t1, t2, t3;
                LDSM_X4(t0, t1, t2, t3, bB + offB[j * 2 + ks]);
                bF[2 * j][0] = t0; bF[2 * j][1] = t1;
                bF[2 * j + 1][0] = t2; bF[2 * j + 1][1] = t3;
            }
#pragma unroll
            for (int mi = 0; mi < 4; mi++)
#pragma unroll
                for (int ni = 0; ni < 8; ni++)
                    MMA_F16(acc[mi][ni], aF[mi], bF[ni]);
        }
    }

    // epilogue: add bias, store fp32
#pragma unroll
    for (int mi = 0; mi < 4; mi++) {
#pragma unroll
        for (int ni = 0; ni < 8; ni++) {
            int col = bn + wn * 64 + ni * 8 + 2 * (lane & 3);
            float2 bias = *(const float2*)(bb + col);
            int m0 = bm + wm * 64 + mi * 16 + (lane >> 2);
            if (m0 < Mm) {
                float2 o = make_float2(acc[mi][ni][0] + bias.x, acc[mi][ni][1] + bias.y);
                *(float2*)(out + (size_t)m0 * Oo + col) = o;
            }
            int m1 = m0 + 8;
            if (m1 < Mm) {
                float2 o = make_float2(acc[mi][ni][2] + bias.x, acc[mi][ni][3] + bias.y);
                *(float2*)(out + (size_t)m1 * Oo + col) = o;
            }
        }
    }
}

// ---------------------------------------------------------------------------
extern "C" void kernel_launch(void* const* d_in, const int* in_sizes, int n_in,
                              void* d_out, int out_size) {
    const float* x  = (const float*)d_in[0];   // (16,1500,1024)
    const float* w  = (const float*)d_in[1];   // (16,8)
    const float* Wb = (const float*)d_in[2];   // (1024,1024)
    const float* bb = (const float*)d_in[3];   // (1024,)
    const float* As = (const float*)d_in[4];   // (8,16,1024) = Acat (128,1024)
    const float* Bs = (const float*)d_in[5];   // (8,1024,16)
    float* out = (float*)d_out;

    cudaFuncSetAttribute(k_lora_h, cudaFuncAttributeMaxDynamicSharedMemorySize, DYN_SMEM);
    cudaFuncSetAttribute(k_main, cudaFuncAttributeMaxDynamicSharedMemorySize, DYN_SMEM);

    k_prep_all<<<1184, 256>>>(x, Wb, As, Bs);

    const int grid_m = (Mm + 127) / 128;  // 188
    k_lora_h<<<grid_m, 256, DYN_SMEM>>>(w);

    dim3 g2(Oo / 128, grid_m);            // (8, 188)
    k_main<<<g2, 128, DYN_SMEM>>>(bb, out);
}

// round 16
// speedup vs baseline: 1.4339x; 1.4339x over previous
#include <cuda_runtime.h>
#include <cuda_fp16.h>
#include <cstdint>

// MASLoRALinear, fp16 HMMA with cp.async 3-stage pipeline. (R11 structure;
// prep x-loop uses streaming ld/st hints + explicit MLP batching.)
//   k_prep_all: xh=half(x), wbh=half(W_base), ah=half(Acat), bch=half(Bcat)
//   k_lora_h:   Hh[m,n] = half( SCALE * w[b(m), n>>4] * (xh @ ah^T)[m,n] )
//   k_main:     out[m,o] = bb[o] + (xh @ wbh^T)[m,o] + (Hh @ bch^T)[m,o]

namespace {
constexpr int Tt = 1500, Cc = 1024, Oo = 1024, Ee = 8, Rr = 16;
constexpr int Mm = 16 * Tt;          // 24000
constexpr int ER = Ee * Rr;          // 128
constexpr float SCALE = 32.0f / 16.0f;
constexpr int STAGE = 16384;         // A 8KB + B 8KB (fp16, BK=32)
constexpr int NSTAGE = 3;
constexpr int DYN_SMEM = NSTAGE * STAGE;
}

__device__ __half g_xh[(size_t)Mm * Cc];     // 24000x1024
__device__ __half g_wbh[(size_t)Oo * Cc];    // 1024x1024
__device__ __half g_ah[(size_t)ER * Cc];     // 128x1024 (Acat)
__device__ __half g_bch[(size_t)Oo * ER];    // 1024x128 (Bcat)
__device__ __half g_Hh[(size_t)Mm * ER];     // 24000x128

// ---------------------------------------------------------------------------
__device__ __forceinline__ uint32_t smem_u32(const void* p) {
    uint32_t a;
    asm("{ .reg .u64 t; cvta.to.shared.u64 t, %1; cvt.u32.u64 %0, t; }" : "=r"(a) : "l"(p));
    return a;
}

#define CP16(s, g) \
    asm volatile("cp.async.cg.shared.global [%0], [%1], 16;" :: "r"(s), "l"(g))
#define CP_COMMIT() asm volatile("cp.async.commit_group;" ::: "memory")
#define CP_WAIT1() asm volatile("cp.async.wait_group 1;" ::: "memory")
#define CP_WAIT0() asm volatile("cp.async.wait_group 0;" ::: "memory")

#define LDSM_X4(r0, r1, r2, r3, a) \
    asm volatile("ldmatrix.sync.aligned.m8n8.x4.shared.b16 {%0,%1,%2,%3}, [%4];" \
                 : "=r"(r0), "=r"(r1), "=r"(r2), "=r"(r3) : "r"(a))

#define MMA_F16(d, a, b) \
    asm volatile("mma.sync.aligned.m16n8k16.row.col.f32.f16.f16.f32 " \
                 "{%0,%1,%2,%3},{%4,%5,%6,%7},{%8,%9},{%0,%1,%2,%3};" \
                 : "+f"((d)[0]), "+f"((d)[1]), "+f"((d)[2]), "+f"((d)[3]) \
                 : "r"((a)[0]), "r"((a)[1]), "r"((a)[2]), "r"((a)[3]), \
                   "r"((b)[0]), "r"((b)[1]))

// swizzled byte offset within an 8KB tile: 64B rows, 4x16B cols, xor swizzle
__device__ __forceinline__ uint32_t swz(int r, int c) {
    return (uint32_t)(r * 64 + ((c ^ ((r >> 1) & 3)) << 4));
}

// one BK=32 chunk: 2 k-steps x (4 m x 4 n) MMAs
__device__ __forceinline__ void compute_chunk(float (&acc)[4][4][4],
                                              uint32_t base,
                                              const uint32_t* offA,
                                              const uint32_t* offB) {
    const uint32_t aB = base, bB = base + 8192u;
#pragma unroll
    for (int ks = 0; ks < 2; ks++) {
        uint32_t aF[4][4], bF[4][2];
#pragma unroll
        for (int mi = 0; mi < 4; mi++)
            LDSM_X4(aF[mi][0], aF[mi][1], aF[mi][2], aF[mi][3], aB + offA[mi * 2 + ks]);
#pragma unroll
        for (int j = 0; j < 2; j++) {
            uint32_t t0, t1, t2, t3;
            LDSM_X4(t0, t1, t2, t3, bB + offB[j * 2 + ks]);
            bF[2 * j][0] = t0; bF[2 * j][1] = t1;
            bF[2 * j + 1][0] = t2; bF[2 * j + 1][1] = t3;
        }
#pragma unroll
        for (int mi = 0; mi < 4; mi++)
#pragma unroll
            for (int ni = 0; ni < 4; ni++)
                MMA_F16(acc[mi][ni], aF[mi], bF[ni]);
    }
}

__device__ __forceinline__ void make_offsets(int lane, int wm, int wn,
                                             uint32_t* offA, uint32_t* offB) {
    int g = lane >> 3, wr = lane & 7;
#pragma unroll
    for (int mi = 0; mi < 4; mi++)
#pragma unroll
        for (int ks = 0; ks < 2; ks++) {
            int r = wm * 64 + mi * 16 + (g & 1) * 8 + wr;
            offA[mi * 2 + ks] = swz(r, ks * 2 + (g >> 1));
        }
#pragma unroll
    for (int j = 0; j < 2; j++)
#pragma unroll
        for (int ks = 0; ks < 2; ks++) {
            int n = wn * 32 + j * 16 + (g >> 1) * 8 + wr;
            offB[j * 2 + ks] = swz(n, ks * 2 + (g & 1));
        }
}

// fp32 float4 -> packed fp16 uint2
__device__ __forceinline__ uint2 cvt4(float4 v) {
    __half2 h0 = __float22half2_rn(make_float2(v.x, v.y));
    __half2 h1 = __float22half2_rn(make_float2(v.z, v.w));
    return make_uint2(*(uint32_t*)&h0, *(uint32_t*)&h1);
}

// ---------------------------------------------------------------------------
// single prep launch. x path: streaming (evict-first) loads/stores, 2-wide MLP.
// ---------------------------------------------------------------------------
__global__ void k_prep_all(const float* __restrict__ x, const float* __restrict__ Wb,
                           const float* __restrict__ As, const float* __restrict__ Bs) {
    const int stride = gridDim.x * blockDim.x;
    const int gtid = blockIdx.x * blockDim.x + threadIdx.x;

    // x: 6,144,000 float4 — streaming, 2 independent loads in flight
    const int NX = Mm * Cc / 4;
    int i = gtid;
    for (; i + stride < NX; i += 2 * stride) {
        float4 v0 = __ldcs((const float4*)(x + (size_t)i * 4));
        float4 v1 = __ldcs((const float4*)(x + (size_t)(i + stride) * 4));
        __stcs((uint2*)(g_xh + (size_t)i * 4), cvt4(v0));
        __stcs((uint2*)(g_xh + (size_t)(i + stride) * 4), cvt4(v1));
    }
    for (; i < NX; i += stride) {
        float4 v = __ldcs((const float4*)(x + (size_t)i * 4));
        __stcs((uint2*)(g_xh + (size_t)i * 4), cvt4(v));
    }
    // Wb: 262,144 float4 (keep cached — reused by k_main from L2)
    for (int j = gtid; j < Oo * Cc / 4; j += stride)
        *(uint2*)(g_wbh + (size_t)j * 4) = cvt4(*(const float4*)(Wb + (size_t)j * 4));
    // Acat: 32,768 float4
    for (int j = gtid; j < ER * Cc / 4; j += stride)
        *(uint2*)(g_ah + (size_t)j * 4) = cvt4(*(const float4*)(As + (size_t)j * 4));
    // Bcat transpose: 131,072 scalars
    for (int idx = gtid; idx < Oo * ER; idx += stride) {
        int o = idx >> 7, n = idx & 127;
        g_bch[idx] = __float2half(Bs[(((size_t)(n >> 4)) * Oo + o) * Rr + (n & 15)]);
    }
}

// ---------------------------------------------------------------------------
// Kernel 1: Hh = gate-scaled (xh @ ah^T), 32 chunks of BK=32  (R11 verbatim)
// ---------------------------------------------------------------------------
__global__ __launch_bounds__(256, 2)
void k_lora_h(const float* __restrict__ w) {
    extern __shared__ char dsm[];
    const uint32_t sb = smem_u32(dsm);
    const int tid = threadIdx.x;
    const int lane = tid & 31, wid = tid >> 5;
    const int wm = wid >> 2, wn = wid & 3;
    const int bm = blockIdx.x * 128;

    const int r0 = tid >> 2, cc4 = tid & 3;
    const __half* xa0 = g_xh + (size_t)min(bm + r0, Mm - 1) * Cc + cc4 * 8;
    const __half* xa1 = g_xh + (size_t)min(bm + r0 + 64, Mm - 1) * Cc + cc4 * 8;
    const __half* ab0 = g_ah + (size_t)r0 * Cc + cc4 * 8;
    const __half* ab1 = g_ah + (size_t)(r0 + 64) * Cc + cc4 * 8;
    const uint32_t o0 = swz(r0, cc4), o1 = swz(r0 + 64, cc4);

    uint32_t offA[8], offB[4];
    make_offsets(lane, wm, wn, offA, offB);

    float acc[4][4][4];
#pragma unroll
    for (int a = 0; a < 4; a++)
#pragma unroll
        for (int b = 0; b < 4; b++)
#pragma unroll
            for (int c = 0; c < 4; c++) acc[a][b][c] = 0.0f;

    const int NCH = 32;
#pragma unroll
    for (int p = 0; p < 2; p++) {
        uint32_t st = sb + (uint32_t)p * STAGE;
        CP16(st + o0, xa0 + p * 32); CP16(st + o1, xa1 + p * 32);
        CP16(st + 8192u + o0, ab0 + p * 32); CP16(st + 8192u + o1, ab1 + p * 32);
        CP_COMMIT();
    }

#pragma unroll 1
    for (int ch = 0; ch < NCH; ch++) {
        if (ch + 1 < NCH) CP_WAIT1(); else CP_WAIT0();
        __syncthreads();
        if (ch + 2 < NCH) {
            uint32_t st = sb + (uint32_t)((ch + 2) % NSTAGE) * STAGE;
            CP16(st + o0, xa0 + (ch + 2) * 32); CP16(st + o1, xa1 + (ch + 2) * 32);
            CP16(st + 8192u + o0, ab0 + (ch + 2) * 32); CP16(st + 8192u + o1, ab1 + (ch + 2) * 32);
            CP_COMMIT();
        }
        compute_chunk(acc, sb + (uint32_t)(ch % NSTAGE) * STAGE, offA, offB);
    }

    // epilogue: scale and store fp16 H
#pragma unroll
    for (int mi = 0; mi < 4; mi++) {
#pragma unroll
        for (int ni = 0; ni < 4; ni++) {
            int n = wn * 32 + ni * 8 + 2 * (lane & 3);
            int e = n >> 4;
            int m0 = bm + wm * 64 + mi * 16 + (lane >> 2);
            if (m0 < Mm) {
                float sw = SCALE * __ldg(&w[(m0 / Tt) * Ee + e]);
                __half2 h = __float22half2_rn(make_float2(acc[mi][ni][0] * sw, acc[mi][ni][1] * sw));
                *(__half2*)(&g_Hh[(size_t)m0 * ER + n]) = h;
            }
            int m1 = m0 + 8;
            if (m1 < Mm) {
                float sw = SCALE * __ldg(&w[(m1 / Tt) * Ee + e]);
                __half2 h = __float22half2_rn(make_float2(acc[mi][ni][2] * sw, acc[mi][ni][3] * sw));
                *(__half2*)(&g_Hh[(size_t)m1 * ER + n]) = h;
            }
        }
    }
}

// ---------------------------------------------------------------------------
// Kernel 2: out = xh @ wbh^T + Hh @ bch^T + bb; 36 chunks  (R11 verbatim)
// ---------------------------------------------------------------------------
__global__ __launch_bounds__(256, 2)
void k_main(const float* __restrict__ bb, float* __restrict__ out) {
    extern __shared__ char dsm[];
    const uint32_t sb = smem_u32(dsm);
    const int tid = threadIdx.x;
    const int lane = tid & 31, wid = tid >> 5;
    const int wm = wid >> 2, wn = wid & 3;
    const int bn = blockIdx.x * 128;
    const int bm = blockIdx.y * 128;

    const int r0 = tid >> 2, cc4 = tid & 3;
    const size_t mA0 = (size_t)min(bm + r0, Mm - 1);
    const size_t mA1 = (size_t)min(bm + r0 + 64, Mm - 1);
    const __half* xa0 = g_xh + mA0 * Cc + cc4 * 8;
    const __half* xa1 = g_xh + mA1 * Cc + cc4 * 8;
    const __half* wb0 = g_wbh + (size_t)(bn + r0) * Cc + cc4 * 8;
    const __half* wb1 = g_wbh + (size_t)(bn + r0 + 64) * Cc + cc4 * 8;
    const __half* ha0 = g_Hh + mA0 * ER + cc4 * 8;
    const __half* ha1 = g_Hh + mA1 * ER + cc4 * 8;
    const __half* bc0 = g_bch + (size_t)(bn + r0) * ER + cc4 * 8;
    const __half* bc1 = g_bch + (size_t)(bn + r0 + 64) * ER + cc4 * 8;
    const uint32_t o0 = swz(r0, cc4), o1 = swz(r0 + 64, cc4);

    uint32_t offA[8], offB[4];
    make_offsets(lane, wm, wn, offA, offB);

    float acc[4][4][4];
#pragma unroll
    for (int a = 0; a < 4; a++)
#pragma unroll
        for (int b = 0; b < 4; b++)
#pragma unroll
            for (int c = 0; c < 4; c++) acc[a][b][c] = 0.0f;

    const int NCH = 36;

    auto issue = [&](int ch) {
        uint32_t st = sb + (uint32_t)(ch % NSTAGE) * STAGE;
        const __half *a0, *a1, *b0, *b1;
        if (ch < 32) {
            a0 = xa0 + ch * 32; a1 = xa1 + ch * 32;
            b0 = wb0 + ch * 32; b1 = wb1 + ch * 32;
        } else {
            int c2 = ch - 32;
            a0 = ha0 + c2 * 32; a1 = ha1 + c2 * 32;
            b0 = bc0 + c2 * 32; b1 = bc1 + c2 * 32;
        }
        CP16(st + o0, a0); CP16(st + o1, a1);
        CP16(st + 8192u + o0, b0); CP16(st + 8192u + o1, b1);
        CP_COMMIT();
    };

    issue(0);
    issue(1);

#pragma unroll 1
    for (int ch = 0; ch < NCH; ch++) {
        if (ch + 1 < NCH) CP_WAIT1(); else CP_WAIT0();
        __syncthreads();
        if (ch + 2 < NCH) issue(ch + 2);
        compute_chunk(acc, sb + (uint32_t)(ch % NSTAGE) * STAGE, offA, offB);
    }

    // epilogue: add bias, store fp32
#pragma unroll
    for (int mi = 0; mi < 4; mi++) {
#pragma unroll
        for (int ni = 0; ni < 4; ni++) {
            int col = bn + wn * 32 + ni * 8 + 2 * (lane & 3);
            float2 bias = *(const float2*)(bb + col);
            int m0 = bm + wm * 64 + mi * 16 + (lane >> 2);
            if (m0 < Mm) {
                float2 o = make_float2(acc[mi][ni][0] + bias.x, acc[mi][ni][1] + bias.y);
                *(float2*)(out + (size_t)m0 * Oo + col) = o;
            }
            int m1 = m0 + 8;
            if (m1 < Mm) {
                float2 o = make_float2(acc[mi][ni][2] + bias.x, acc[mi][ni][3] + bias.y);
                *(float2*)(out + (size_t)m1 * Oo + col) = o;
            }
        }
    }
}

// ---------------------------------------------------------------------------
extern "C" void kernel_launch(void* const* d_in, const int* in_sizes, int n_in,
                              void* d_out, int out_size) {
    const float* x  = (const float*)d_in[0];   // (16,1500,1024)
    const float* w  = (const float*)d_in[1];   // (16,8)
    const float* Wb = (const float*)d_in[2];   // (1024,1024)
    const float* bb = (const float*)d_in[3];   // (1024,)
    const float* As = (const float*)d_in[4];   // (8,16,1024) = Acat (128,1024)
    const float* Bs = (const float*)d_in[5];   // (8,1024,16)
    float* out = (float*)d_out;

    cudaFuncSetAttribute(k_lora_h, cudaFuncAttributeMaxDynamicSharedMemorySize, DYN_SMEM);
    cudaFuncSetAttribute(k_main, cudaFuncAttributeMaxDynamicSharedMemorySize, DYN_SMEM);

    // ONE prep launch for all conversions (grid-stride, streaming x path)
    k_prep_all<<<1184, 256>>>(x, Wb, As, Bs);

    const int grid_m = (Mm + 127) / 128;  // 188
    k_lora_h<<<grid_m, 256, DYN_SMEM>>>(w);

    dim3 g2(Oo / 128, grid_m);            // (8, 188)
    k_main<<<g2, 256, DYN_SMEM>>>(bb, out);
}

// round 17
// speedup vs baseline: 1.4350x; 1.0008x over previous
#include <cuda_runtime.h>
#include <cuda_fp16.h>
#include <cstdint>

// MASLoRALinear, fp16 HMMA. R16 prep; lora + main FUSED into one kernel:
// producer CTAs (bid 0..187) compute Hh tiles and release per-tile flags;
// consumer CTAs run the 36-chunk GEMM and acquire the flag just before
// issuing chunk 32 (the first Hh-dependent chunk).

namespace {
constexpr int Tt = 1500, Cc = 1024, Oo = 1024, Ee = 8, Rr = 16;
constexpr int Mm = 16 * Tt;          // 24000
constexpr int ER = Ee * Rr;          // 128
constexpr float SCALE = 32.0f / 16.0f;
constexpr int STAGE = 16384;         // A 8KB + B 8KB (fp16, BK=32)
constexpr int NSTAGE = 3;
constexpr int DYN_SMEM = NSTAGE * STAGE;
constexpr int GRID_L = 188;          // lora producer CTAs (M-tiles)
}

__device__ __half g_xh[(size_t)Mm * Cc];     // 24000x1024
__device__ __half g_wbh[(size_t)Oo * Cc];    // 1024x1024
__device__ __half g_ah[(size_t)ER * Cc];     // 128x1024 (Acat)
__device__ __half g_bch[(size_t)Oo * ER];    // 1024x128 (Bcat)
__device__ __half g_Hh[(size_t)Mm * ER];     // 24000x128
__device__ int    g_flag[GRID_L];            // per-M-tile Hh-ready flags

// ---------------------------------------------------------------------------
__device__ __forceinline__ uint32_t smem_u32(const void* p) {
    uint32_t a;
    asm("{ .reg .u64 t; cvta.to.shared.u64 t, %1; cvt.u32.u64 %0, t; }" : "=r"(a) : "l"(p));
    return a;
}

#define CP16(s, g) \
    asm volatile("cp.async.cg.shared.global [%0], [%1], 16;" :: "r"(s), "l"(g))
#define CP_COMMIT() asm volatile("cp.async.commit_group;" ::: "memory")
#define CP_WAIT1() asm volatile("cp.async.wait_group 1;" ::: "memory")
#define CP_WAIT0() asm volatile("cp.async.wait_group 0;" ::: "memory")

#define LDSM_X4(r0, r1, r2, r3, a) \
    asm volatile("ldmatrix.sync.aligned.m8n8.x4.shared.b16 {%0,%1,%2,%3}, [%4];" \
                 : "=r"(r0), "=r"(r1), "=r"(r2), "=r"(r3) : "r"(a))

#define MMA_F16(d, a, b) \
    asm volatile("mma.sync.aligned.m16n8k16.row.col.f32.f16.f16.f32 " \
                 "{%0,%1,%2,%3},{%4,%5,%6,%7},{%8,%9},{%0,%1,%2,%3};" \
                 : "+f"((d)[0]), "+f"((d)[1]), "+f"((d)[2]), "+f"((d)[3]) \
                 : "r"((a)[0]), "r"((a)[1]), "r"((a)[2]), "r"((a)[3]), \
                   "r"((b)[0]), "r"((b)[1]))

// swizzled byte offset within an 8KB tile: 64B rows, 4x16B cols, xor swizzle
__device__ __forceinline__ uint32_t swz(int r, int c) {
    return (uint32_t)(r * 64 + ((c ^ ((r >> 1) & 3)) << 4));
}

// one BK=32 chunk: 2 k-steps x (4 m x 4 n) MMAs
__device__ __forceinline__ void compute_chunk(float (&acc)[4][4][4],
                                              uint32_t base,
                                              const uint32_t* offA,
                                              const uint32_t* offB) {
    const uint32_t aB = base, bB = base + 8192u;
#pragma unroll
    for (int ks = 0; ks < 2; ks++) {
        uint32_t aF[4][4], bF[4][2];
#pragma unroll
        for (int mi = 0; mi < 4; mi++)
            LDSM_X4(aF[mi][0], aF[mi][1], aF[mi][2], aF[mi][3], aB + offA[mi * 2 + ks]);
#pragma unroll
        for (int j = 0; j < 2; j++) {
            uint32_t t0, t1, t2, t3;
            LDSM_X4(t0, t1, t2, t3, bB + offB[j * 2 + ks]);
            bF[2 * j][0] = t0; bF[2 * j][1] = t1;
            bF[2 * j + 1][0] = t2; bF[2 * j + 1][1] = t3;
        }
#pragma unroll
        for (int mi = 0; mi < 4; mi++)
#pragma unroll
            for (int ni = 0; ni < 4; ni++)
                MMA_F16(acc[mi][ni], aF[mi], bF[ni]);
    }
}

__device__ __forceinline__ void make_offsets(int lane, int wm, int wn,
                                             uint32_t* offA, uint32_t* offB) {
    int g = lane >> 3, wr = lane & 7;
#pragma unroll
    for (int mi = 0; mi < 4; mi++)
#pragma unroll
        for (int ks = 0; ks < 2; ks++) {
            int r = wm * 64 + mi * 16 + (g & 1) * 8 + wr;
            offA[mi * 2 + ks] = swz(r, ks * 2 + (g >> 1));
        }
#pragma unroll
    for (int j = 0; j < 2; j++)
#pragma unroll
        for (int ks = 0; ks < 2; ks++) {
            int n = wn * 32 + j * 16 + (g >> 1) * 8 + wr;
            offB[j * 2 + ks] = swz(n, ks * 2 + (g & 1));
        }
}

__device__ __forceinline__ uint2 cvt4(float4 v) {
    __half2 h0 = __float22half2_rn(make_float2(v.x, v.y));
    __half2 h1 = __float22half2_rn(make_float2(v.z, v.w));
    return make_uint2(*(uint32_t*)&h0, *(uint32_t*)&h1);
}

// ---------------------------------------------------------------------------
// single prep launch: conversions + flag reset  (R16 verbatim + flags)
// ---------------------------------------------------------------------------
__global__ void k_prep_all(const float* __restrict__ x, const float* __restrict__ Wb,
                           const float* __restrict__ As, const float* __restrict__ Bs) {
    const int stride = gridDim.x * blockDim.x;
    const int gtid = blockIdx.x * blockDim.x + threadIdx.x;

    if (gtid < GRID_L) g_flag[gtid] = 0;

    const int NX = Mm * Cc / 4;
    int i = gtid;
    for (; i + stride < NX; i += 2 * stride) {
        float4 v0 = __ldcs((const float4*)(x + (size_t)i * 4));
        float4 v1 = __ldcs((const float4*)(x + (size_t)(i + stride) * 4));
        __stcs((uint2*)(g_xh + (size_t)i * 4), cvt4(v0));
        __stcs((uint2*)(g_xh + (size_t)(i + stride) * 4), cvt4(v1));
    }
    for (; i < NX; i += stride) {
        float4 v = __ldcs((const float4*)(x + (size_t)i * 4));
        __stcs((uint2*)(g_xh + (size_t)i * 4), cvt4(v));
    }
    for (int j = gtid; j < Oo * Cc / 4; j += stride)
        *(uint2*)(g_wbh + (size_t)j * 4) = cvt4(*(const float4*)(Wb + (size_t)j * 4));
    for (int j = gtid; j < ER * Cc / 4; j += stride)
        *(uint2*)(g_ah + (size_t)j * 4) = cvt4(*(const float4*)(As + (size_t)j * 4));
    for (int idx = gtid; idx < Oo * ER; idx += stride) {
        int o = idx >> 7, n = idx & 127;
        g_bch[idx] = __float2half(Bs[(((size_t)(n >> 4)) * Oo + o) * Rr + (n & 15)]);
    }
}

// ---------------------------------------------------------------------------
// FUSED kernel: bid < GRID_L -> lora producer; else -> main consumer
// ---------------------------------------------------------------------------
__global__ __launch_bounds__(256, 2)
void k_fused(const float* __restrict__ w, const float* __restrict__ bb,
             float* __restrict__ out) {
    extern __shared__ char dsm[];
    const uint32_t sb = smem_u32(dsm);
    const int tid = threadIdx.x;
    const int lane = tid & 31, wid = tid >> 5;
    const int wm = wid >> 2, wn = wid & 3;
    const int bid = blockIdx.x;

    uint32_t offA[8], offB[4];
    make_offsets(lane, wm, wn, offA, offB);

    float acc[4][4][4];
#pragma unroll
    for (int a = 0; a < 4; a++)
#pragma unroll
        for (int b = 0; b < 4; b++)
#pragma unroll
            for (int c = 0; c < 4; c++) acc[a][b][c] = 0.0f;

    const int r0 = tid >> 2, cc4 = tid & 3;
    const uint32_t o0 = swz(r0, cc4), o1 = swz(r0 + 64, cc4);

    if (bid < GRID_L) {
        // ---------------- lora producer: Hh tile [bm, bm+128) ----------------
        const int bm = bid * 128;
        const __half* xa0 = g_xh + (size_t)min(bm + r0, Mm - 1) * Cc + cc4 * 8;
        const __half* xa1 = g_xh + (size_t)min(bm + r0 + 64, Mm - 1) * Cc + cc4 * 8;
        const __half* ab0 = g_ah + (size_t)r0 * Cc + cc4 * 8;
        const __half* ab1 = g_ah + (size_t)(r0 + 64) * Cc + cc4 * 8;

        const int NCH = 32;
#pragma unroll
        for (int p = 0; p < 2; p++) {
            uint32_t st = sb + (uint32_t)p * STAGE;
            CP16(st + o0, xa0 + p * 32); CP16(st + o1, xa1 + p * 32);
            CP16(st + 8192u + o0, ab0 + p * 32); CP16(st + 8192u + o1, ab1 + p * 32);
            CP_COMMIT();
        }
#pragma unroll 1
        for (int ch = 0; ch < NCH; ch++) {
            if (ch + 1 < NCH) CP_WAIT1(); else CP_WAIT0();
            __syncthreads();
            if (ch + 2 < NCH) {
                uint32_t st = sb + (uint32_t)((ch + 2) % NSTAGE) * STAGE;
                CP16(st + o0, xa0 + (ch + 2) * 32); CP16(st + o1, xa1 + (ch + 2) * 32);
                CP16(st + 8192u + o0, ab0 + (ch + 2) * 32); CP16(st + 8192u + o1, ab1 + (ch + 2) * 32);
                CP_COMMIT();
            }
            compute_chunk(acc, sb + (uint32_t)(ch % NSTAGE) * STAGE, offA, offB);
        }

        // epilogue: scale, store fp16 Hh, then release flag
#pragma unroll
        for (int mi = 0; mi < 4; mi++) {
#pragma unroll
            for (int ni = 0; ni < 4; ni++) {
                int n = wn * 32 + ni * 8 + 2 * (lane & 3);
                int e = n >> 4;
                int m0 = bm + wm * 64 + mi * 16 + (lane >> 2);
                if (m0 < Mm) {
                    float sw = SCALE * __ldg(&w[(m0 / Tt) * Ee + e]);
                    __half2 h = __float22half2_rn(make_float2(acc[mi][ni][0] * sw, acc[mi][ni][1] * sw));
                    *(__half2*)(&g_Hh[(size_t)m0 * ER + n]) = h;
                }
                int m1 = m0 + 8;
                if (m1 < Mm) {
                    float sw = SCALE * __ldg(&w[(m1 / Tt) * Ee + e]);
                    __half2 h = __float22half2_rn(make_float2(acc[mi][ni][2] * sw, acc[mi][ni][3] * sw));
                    *(__half2*)(&g_Hh[(size_t)m1 * ER + n]) = h;
                }
            }
        }
        __threadfence();
        __syncthreads();
        if (tid == 0) atomicExch(&g_flag[bid], 1);
    } else {
        // ---------------- main consumer ----------------
        const int t = bid - GRID_L;
        const int bn = (t & 7) * 128;        // N-tile fastest (x-tile L2 reuse)
        const int bm = (t >> 3) * 128;
        const int mt = t >> 3;               // flag index

        const size_t mA0 = (size_t)min(bm + r0, Mm - 1);
        const size_t mA1 = (size_t)min(bm + r0 + 64, Mm - 1);
        const __half* xa0 = g_xh + mA0 * Cc + cc4 * 8;
        const __half* xa1 = g_xh + mA1 * Cc + cc4 * 8;
        const __half* wb0 = g_wbh + (size_t)(bn + r0) * Cc + cc4 * 8;
        const __half* wb1 = g_wbh + (size_t)(bn + r0 + 64) * Cc + cc4 * 8;
        const __half* ha0 = g_Hh + mA0 * ER + cc4 * 8;
        const __half* ha1 = g_Hh + mA1 * ER + cc4 * 8;
        const __half* bc0 = g_bch + (size_t)(bn + r0) * ER + cc4 * 8;
        const __half* bc1 = g_bch + (size_t)(bn + r0 + 64) * ER + cc4 * 8;

        const int NCH = 36;
        auto issue = [&](int ch) {
            uint32_t st = sb + (uint32_t)(ch % NSTAGE) * STAGE;
            const __half *a0, *a1, *b0, *b1;
            if (ch < 32) {
                a0 = xa0 + ch * 32; a1 = xa1 + ch * 32;
                b0 = wb0 + ch * 32; b1 = wb1 + ch * 32;
            } else {
                int c2 = ch - 32;
                a0 = ha0 + c2 * 32; a1 = ha1 + c2 * 32;
                b0 = bc0 + c2 * 32; b1 = bc1 + c2 * 32;
            }
            CP16(st + o0, a0); CP16(st + o1, a1);
            CP16(st + 8192u + o0, b0); CP16(st + 8192u + o1, b1);
            CP_COMMIT();
        };

        issue(0);
        issue(1);

#pragma unroll 1
        for (int ch = 0; ch < NCH; ch++) {
            if (ch + 1 < NCH) CP_WAIT1(); else CP_WAIT0();
            __syncthreads();
            if (ch + 2 < NCH) {
                if (ch + 2 == 32) {
                    // acquire Hh tile before first Hh-dependent prefetch
                    if (tid == 0)
                        while (atomicAdd(&g_flag[mt], 0) == 0) __nanosleep(64);
                    __syncthreads();
                    __threadfence();
                }
                issue(ch + 2);
            }
            compute_chunk(acc, sb + (uint32_t)(ch % NSTAGE) * STAGE, offA, offB);
        }

        // epilogue: add bias, store fp32
#pragma unroll
        for (int mi = 0; mi < 4; mi++) {
#pragma unroll
            for (int ni = 0; ni < 4; ni++) {
                int col = bn + wn * 32 + ni * 8 + 2 * (lane & 3);
                float2 bias = *(const float2*)(bb + col);
                int m0 = bm + wm * 64 + mi * 16 + (lane >> 2);
                if (m0 < Mm) {
                    float2 o = make_float2(acc[mi][ni][0] + bias.x, acc[mi][ni][1] + bias.y);
                    *(float2*)(out + (size_t)m0 * Oo + col) = o;
                }
                int m1 = m0 + 8;
                if (m1 < Mm) {
                    float2 o = make_float2(acc[mi][ni][2] + bias.x, acc[mi][ni][3] + bias.y);
                    *(float2*)(out + (size_t)m1 * Oo + col) = o;
                }
            }
        }
    }
}

// ---------------------------------------------------------------------------
extern "C" void kernel_launch(void* const* d_in, const int* in_sizes, int n_in,
                              void* d_out, int out_size) {
    const float* x  = (const float*)d_in[0];   // (16,1500,1024)
    const float* w  = (const float*)d_in[1];   // (16,8)
    const float* Wb = (const float*)d_in[2];   // (1024,1024)
    const float* bb = (const float*)d_in[3];   // (1024,)
    const float* As = (const float*)d_in[4];   // (8,16,1024) = Acat (128,1024)
    const float* Bs = (const float*)d_in[5];   // (8,1024,16)
    float* out = (float*)d_out;

    cudaFuncSetAttribute(k_fused, cudaFuncAttributeMaxDynamicSharedMemorySize, DYN_SMEM);

    // prep: conversions + flag reset (graph-replay deterministic)
    k_prep_all<<<1184, 256>>>(x, Wb, As, Bs);

    // fused: 188 lora producers first, then 1504 main consumers
    k_fused<<<GRID_L + 8 * GRID_L, 256, DYN_SMEM>>>(w, bb, out);
}